// round 4
// baseline (speedup 1.0000x reference)
#include <cuda_runtime.h>
#include <cstdint>

#define B_TOT   4096
#define K_STEPS 512
#define U_DIM   3
#define P_DIM   5
#define H_DIM   128
#define L_DIM   32
#define M_ROWS  32
#define THREADS 512

typedef unsigned long long u64;

// Transposed-weight scratch (filled by prep kernel each launch; deterministic)
__device__ __align__(16) float g_whh_t[128 * 384];  // [kk][gate*128 + j]
__device__ __align__(16) float g_wih_j[128 * 96];   // [j][gate*32 + l]

__global__ void prep_kernel(const float* __restrict__ W_ih,
                            const float* __restrict__ W_hh) {
    int i = blockIdx.x * blockDim.x + threadIdx.x;
    if (i < 384 * 128) {
        int o = i / 128, kk = i % 128;
        g_whh_t[kk * 384 + o] = W_hh[o * 128 + kk];
    }
    if (i < 128 * 96) {
        int j = i / 96, rem = i % 96;
        int g = rem / 32, l = rem % 32;
        g_wih_j[i] = W_ih[(g * 128 + j) * 32 + l];
    }
}

__device__ __forceinline__ float sigmoidf_(float x) {
    x = fminf(fmaxf(x, -30.f), 30.f);
    return __fdividef(1.f, 1.f + __expf(-x));
}
__device__ __forceinline__ float tanhf_(float x) {
    x = fminf(fmaxf(x, -15.f), 15.f);
    float e = __expf(2.f * x);
    return __fdividef(e - 1.f, e + 1.f);
}

__device__ __forceinline__ u64 pack2(float a, float b) {
    u64 r; asm("mov.b64 %0,{%1,%2};" : "=l"(r) : "f"(a), "f"(b)); return r;
}
__device__ __forceinline__ u64 dup2(float a) { return pack2(a, a); }
__device__ __forceinline__ void unpack2(u64 v, float& a, float& b) {
    asm("mov.b64 {%0,%1},%2;" : "=f"(a), "=f"(b) : "l"(v));
}
__device__ __forceinline__ u64 fma2(u64 a, u64 b, u64 c) {
    u64 d; asm("fma.rn.f32x2 %0,%1,%2,%3;" : "=l"(d) : "l"(a), "l"(b), "l"(c));
    return d;
}

__device__ __forceinline__ void rhs5(const float* __restrict__ y,
                                     const float* __restrict__ th,
                                     float* __restrict__ d) {
    float A = y[0], D = y[1], G = y[2], J = y[3], M = y[4];
    float f1 = th[0] * A - th[4] * D;
    float f2 = th[1] * D - th[5] * G;
    float f3 = th[2] * G - th[6] * J;
    float f4 = th[3] * J - th[7] * M;
    d[0] = -f1; d[1] = f1 - f2; d[2] = f2 - f3; d[3] = f3 - f4; d[4] = f4;
}

// smem (floats): whh 49152 | h_t 128*36 | x_t 32*36 | y_s 256 | th_s 256 | u_s 128 | dt_s 32
#define SM_TOTAL_FLOATS 55584

__global__ void __launch_bounds__(THREADS, 1)
rnn_main(const float* __restrict__ y0,
         const float* __restrict__ u_seq,
         const float* __restrict__ dt_seq,
         const float* __restrict__ lift_W,
         const float* __restrict__ lift_b,
         const float* __restrict__ b_ih,
         const float* __restrict__ b_hh,
         const float* __restrict__ head_W,
         const float* __restrict__ head_b,
         const float* __restrict__ ujump,
         float* __restrict__ y_out,
         float* __restrict__ theta_out) {
    extern __shared__ float sm[];
    float* whh  = sm;                 // 49152
    float* h_t  = whh + 49152;        // 4608 (pitch 36)
    float* x_t  = h_t + 4608;         // 1152 (pitch 36)
    float* y_s  = x_t + 1152;         // 256
    float* th_s = y_s + 256;          // 256
    float* u_s  = th_s + 256;         // 128
    float* dt_s = u_s + 128;          // 32

    const int t    = threadIdx.x;
    const int w    = t >> 5;
    const int lane = t & 31;
    const int j    = w * 8 + (lane >> 2);   // this thread's hidden index
    const int rq   = (lane & 3) << 3;       // row quarter start: 0/8/16/24
    const int R0   = blockIdx.x * M_ROWS;

    // Stage weights into smem
    {
        const float4* src = (const float4*)g_whh_t;
        float4* dst = (float4*)whh;
        #pragma unroll 4
        for (int i = t; i < 49152 / 4; i += THREADS) dst[i] = src[i];
    }
    for (int i = t; i < 4608; i += THREADS) h_t[i] = 0.f;
    if (t < M_ROWS) {
        #pragma unroll
        for (int i = 0; i < 5; ++i)
            y_s[t * 8 + i] = y0[(R0 + t) * 5 + i] + 0.01f;
    }

    // Per-thread biases (j fixed for whole sequence), pre-duplicated
    const u64 bR2  = dup2(b_ih[j] + b_hh[j]);
    const u64 bZ2  = dup2(b_ih[128 + j] + b_hh[128 + j]);
    const u64 bNI2 = dup2(b_ih[256 + j]);
    const u64 bNH2 = dup2(b_hh[256 + j]);
    const float* wj = g_wih_j + j * 96;
    __syncthreads();

    for (int k = 0; k < K_STEPS; ++k) {
        // ---------- stage 1: lift + silu -> x_t[l][r] (2 l's per thread) ----------
        {
            int r  = t & 31;
            int lg = t >> 5;            // 0..15
            float f[8];
            const float* up = u_seq + ((size_t)(R0 + r) * K_STEPS + k) * U_DIM;
            f[0] = up[0]; f[1] = up[1]; f[2] = up[2];
            #pragma unroll
            for (int i = 0; i < 5; ++i) f[3 + i] = y_s[r * 8 + i];
            if (lg == 0) {
                u_s[r * 4 + 0] = f[0];
                u_s[r * 4 + 1] = f[1];
                u_s[r * 4 + 2] = f[2];
                dt_s[r] = dt_seq[(size_t)(R0 + r) * K_STEPS + k];
            }
            #pragma unroll
            for (int c = 0; c < 2; ++c) {
                int l = lg * 2 + c;
                float acc = lift_b[l];
                #pragma unroll
                for (int q = 0; q < 8; ++q)
                    acc = fmaf(lift_W[l * 8 + q], f[q], acc);
                x_t[l * 36 + r] = acc * sigmoidf_(acc);
            }
        }
        __syncthreads();

        // ---------- stage 2: GEMMs (f32x2, row pairs packed; 8 rows/thread) ----------
        u64 aR[4], aZ[4], aNI[4], aNH[4];
        #pragma unroll
        for (int i = 0; i < 4; ++i) {
            aR[i] = bR2; aZ[i] = bZ2; aNI[i] = bNI2; aNH[i] = bNH2;
        }

        // gi: x in smem, W_ih[j] rows from L2
        {
            float4 wR4 = __ldg((const float4*)(wj + 0));
            float4 wZ4 = __ldg((const float4*)(wj + 32));
            float4 wN4 = __ldg((const float4*)(wj + 64));
            #pragma unroll
            for (int l0 = 0; l0 < 32; l0 += 4) {
                float wRv[4], wZv[4], wNv[4];
                *(float4*)wRv = wR4; *(float4*)wZv = wZ4; *(float4*)wNv = wN4;
                if (l0 + 4 < 32) {
                    wR4 = __ldg((const float4*)(wj + l0 + 4));
                    wZ4 = __ldg((const float4*)(wj + 32 + l0 + 4));
                    wN4 = __ldg((const float4*)(wj + 64 + l0 + 4));
                }
                #pragma unroll
                for (int dl = 0; dl < 4; ++dl) {
                    const int l = l0 + dl;
                    const ulonglong2* xp = (const ulonglong2*)(x_t + l * 36 + rq);
                    ulonglong2 x01 = xp[0], x23 = xp[1];
                    u64 xv[4] = {x01.x, x01.y, x23.x, x23.y};
                    u64 wr2 = dup2(wRv[dl]), wz2 = dup2(wZv[dl]), wn2 = dup2(wNv[dl]);
                    #pragma unroll
                    for (int i = 0; i < 4; ++i) {
                        aR[i]  = fma2(xv[i], wr2, aR[i]);
                        aZ[i]  = fma2(xv[i], wz2, aZ[i]);
                        aNI[i] = fma2(xv[i], wn2, aNI[i]);
                    }
                }
            }
        }

        // gh: h + W_hh from smem. 4-lane groups share j (broadcast weights);
        // quarter-row blocks per lane.
        #pragma unroll 4
        for (int kk = 0; kk < 128; ++kk) {
            const float* wrow = whh + kk * 384 + j;
            u64 wr2 = dup2(wrow[0]);
            u64 wz2 = dup2(wrow[128]);
            u64 wn2 = dup2(wrow[256]);
            const ulonglong2* hp = (const ulonglong2*)(h_t + kk * 36 + rq);
            ulonglong2 h01 = hp[0], h23 = hp[1];
            u64 hv[4] = {h01.x, h01.y, h23.x, h23.y};
            #pragma unroll
            for (int i = 0; i < 4; ++i) {
                aR[i]  = fma2(hv[i], wr2, aR[i]);
                aZ[i]  = fma2(hv[i], wz2, aZ[i]);
                aNH[i] = fma2(hv[i], wn2, aNH[i]);
            }
        }

        // gates + h update (this thread owns h[j][rq..rq+7])
        float hn[8];
        {
            const ulonglong2* hop = (const ulonglong2*)(h_t + j * 36 + rq);
            ulonglong2 ho01 = hop[0], ho23 = hop[1];
            u64 hov[4] = {ho01.x, ho01.y, ho23.x, ho23.y};
            #pragma unroll
            for (int i = 0; i < 4; ++i) {
                float r0, r1, z0, z1, ni0, ni1, nh0, nh1, h0, h1;
                unpack2(aR[i], r0, r1);
                unpack2(aZ[i], z0, z1);
                unpack2(aNI[i], ni0, ni1);
                unpack2(aNH[i], nh0, nh1);
                unpack2(hov[i], h0, h1);
                float gr0 = sigmoidf_(r0), gr1 = sigmoidf_(r1);
                float gz0 = sigmoidf_(z0), gz1 = sigmoidf_(z1);
                float gn0 = tanhf_(fmaf(gr0, nh0, ni0));
                float gn1 = tanhf_(fmaf(gr1, nh1, ni1));
                hn[2 * i]     = (1.f - gz0) * gn0 + gz0 * h0;
                hn[2 * i + 1] = (1.f - gz1) * gn1 + gz1 * h1;
            }
        }

        __syncthreads();  // all reads of h_t complete
        {
            float4* hdst = (float4*)(h_t + j * 36 + rq);
            hdst[0] = make_float4(hn[0], hn[1], hn[2], hn[3]);
            hdst[1] = make_float4(hn[4], hn[5], hn[6], hn[7]);
        }
        __syncthreads();

        // ---------- stage 3: head -> theta ----------
        if (t < 256) {
            int r = t >> 3, c8 = t & 7;
            float acc = head_b[c8];
            #pragma unroll 4
            for (int jj = 0; jj < 128; jj += 4) {
                const float4 wv = __ldg((const float4*)(head_W + c8 * 128 + jj));
                acc = fmaf(wv.x, h_t[(jj + 0) * 36 + r], acc);
                acc = fmaf(wv.y, h_t[(jj + 1) * 36 + r], acc);
                acc = fmaf(wv.z, h_t[(jj + 2) * 36 + r], acc);
                acc = fmaf(wv.w, h_t[(jj + 3) * 36 + r], acc);
            }
            float th = 0.01f + 2.99f * sigmoidf_(acc);
            th_s[r * 8 + c8] = th;
            theta_out[(((size_t)(R0 + r)) * K_STEPS + k) * 8 + c8] = th;
        }
        __syncthreads();

        // ---------- stage 4: RK4 ODE (one lane per row) ----------
        if (t < 32) {
            int r = t;
            float y[5];
            #pragma unroll
            for (int i = 0; i < 5; ++i) y[i] = y_s[r * 8 + i];
            float u0 = u_s[r * 4 + 0], u1 = u_s[r * 4 + 1], u2 = u_s[r * 4 + 2];
            #pragma unroll
            for (int p = 0; p < 5; ++p)
                y[p] += u0 * ujump[p] + u1 * ujump[5 + p] + u2 * ujump[10 + p];
            float th[8];
            #pragma unroll
            for (int i = 0; i < 8; ++i) th[i] = th_s[r * 8 + i];
            float hs = dt_s[r] * 0.1f;
            float hh = 0.5f * hs;
            float h6 = hs * (1.f / 6.f);
            for (int s = 0; s < 10; ++s) {
                float k1[5], k2[5], k3[5], k4[5], yt[5];
                rhs5(y, th, k1);
                #pragma unroll
                for (int i = 0; i < 5; ++i) yt[i] = fmaf(hh, k1[i], y[i]);
                rhs5(yt, th, k2);
                #pragma unroll
                for (int i = 0; i < 5; ++i) yt[i] = fmaf(hh, k2[i], y[i]);
                rhs5(yt, th, k3);
                #pragma unroll
                for (int i = 0; i < 5; ++i) yt[i] = fmaf(hs, k3[i], y[i]);
                rhs5(yt, th, k4);
                #pragma unroll
                for (int i = 0; i < 5; ++i) {
                    float incr = k1[i] + 2.f * k2[i] + 2.f * k3[i] + k4[i];
                    y[i] = fmaxf(fmaf(h6, incr, y[i]), 0.f);
                }
            }
            #pragma unroll
            for (int i = 0; i < 5; ++i) {
                y_s[r * 8 + i] = y[i];
                y_out[(((size_t)(R0 + r)) * K_STEPS + k) * 5 + i] = y[i];
            }
        }
        __syncthreads();
    }
}

extern "C" void kernel_launch(void* const* d_in, const int* in_sizes, int n_in,
                              void* d_out, int out_size) {
    const float* y0     = (const float*)d_in[0];
    const float* u_seq  = (const float*)d_in[1];
    const float* dt_seq = (const float*)d_in[2];
    const float* lift_W = (const float*)d_in[3];
    const float* lift_b = (const float*)d_in[4];
    const float* W_ih   = (const float*)d_in[5];
    const float* W_hh   = (const float*)d_in[6];
    const float* b_ih   = (const float*)d_in[7];
    const float* b_hh   = (const float*)d_in[8];
    const float* head_W = (const float*)d_in[9];
    const float* head_b = (const float*)d_in[10];
    const float* ujump  = (const float*)d_in[11];

    float* y_out     = (float*)d_out;
    float* theta_out = y_out + (size_t)B_TOT * K_STEPS * 5;

    prep_kernel<<<(384 * 128 + 255) / 256, 256>>>(W_ih, W_hh);

    size_t smem_bytes = (size_t)SM_TOTAL_FLOATS * sizeof(float);  // 222336
    cudaFuncSetAttribute(rnn_main, cudaFuncAttributeMaxDynamicSharedMemorySize,
                         (int)smem_bytes);
    rnn_main<<<B_TOT / M_ROWS, THREADS, smem_bytes>>>(
        y0, u_seq, dt_seq, lift_W, lift_b, b_ih, b_hh, head_W, head_b, ujump,
        y_out, theta_out);
}

// round 5
// speedup vs baseline: 1.0015x; 1.0015x over previous
#include <cuda_runtime.h>
#include <cstdint>

#define B_TOT   4096
#define K_STEPS 512
#define U_DIM   3
#define P_DIM   5
#define H_DIM   128
#define L_DIM   32
#define M_ROWS  32
#define THREADS 512

typedef unsigned long long u64;

// Transposed-weight scratch (filled by prep kernel each launch; deterministic)
__device__ __align__(16) float g_whh_t[128 * 384];  // [kk][gate*128 + j]
__device__ __align__(16) float g_wih_j[128 * 96];   // [j][gate*32 + l]

__global__ void prep_kernel(const float* __restrict__ W_ih,
                            const float* __restrict__ W_hh) {
    int i = blockIdx.x * blockDim.x + threadIdx.x;
    if (i < 384 * 128) {
        int o = i / 128, kk = i % 128;
        g_whh_t[kk * 384 + o] = W_hh[o * 128 + kk];
    }
    if (i < 128 * 96) {
        int j = i / 96, rem = i % 96;
        int g = rem / 32, l = rem % 32;
        g_wih_j[i] = W_ih[(g * 128 + j) * 32 + l];
    }
}

__device__ __forceinline__ float sigmoidf_(float x) {
    x = fminf(fmaxf(x, -30.f), 30.f);
    return __fdividef(1.f, 1.f + __expf(-x));
}
__device__ __forceinline__ float tanhf_(float x) {
    x = fminf(fmaxf(x, -15.f), 15.f);
    float e = __expf(2.f * x);
    return __fdividef(e - 1.f, e + 1.f);
}

__device__ __forceinline__ u64 pack2(float a, float b) {
    u64 r; asm("mov.b64 %0,{%1,%2};" : "=l"(r) : "f"(a), "f"(b)); return r;
}
__device__ __forceinline__ u64 dup2(float a) { return pack2(a, a); }
__device__ __forceinline__ void unpack2(u64 v, float& a, float& b) {
    asm("mov.b64 {%0,%1},%2;" : "=f"(a), "=f"(b) : "l"(v));
}
__device__ __forceinline__ u64 fma2(u64 a, u64 b, u64 c) {
    u64 d; asm("fma.rn.f32x2 %0,%1,%2,%3;" : "=l"(d) : "l"(a), "l"(b), "l"(c));
    return d;
}

__device__ __forceinline__ void rhs5(const float* __restrict__ y,
                                     const float* __restrict__ th,
                                     float* __restrict__ d) {
    float A = y[0], D = y[1], G = y[2], J = y[3], M = y[4];
    float f1 = th[0] * A - th[4] * D;
    float f2 = th[1] * D - th[5] * G;
    float f3 = th[2] * G - th[6] * J;
    float f4 = th[3] * J - th[7] * M;
    d[0] = -f1; d[1] = f1 - f2; d[2] = f2 - f3; d[3] = f3 - f4; d[4] = f4;
}

// smem (floats): whh 49152 | h_t 128*36 | x_t 32*36 | y_s 256 | th_s 256 | u_s 128 | dt_s 32
#define SM_TOTAL_FLOATS 55584

__global__ void __launch_bounds__(THREADS, 1)
rnn_main(const float* __restrict__ y0,
         const float* __restrict__ u_seq,
         const float* __restrict__ dt_seq,
         const float* __restrict__ lift_W,
         const float* __restrict__ lift_b,
         const float* __restrict__ b_ih,
         const float* __restrict__ b_hh,
         const float* __restrict__ head_W,
         const float* __restrict__ head_b,
         const float* __restrict__ ujump,
         float* __restrict__ y_out,
         float* __restrict__ theta_out) {
    extern __shared__ float sm[];
    float* whh  = sm;                 // 49152
    float* h_t  = whh + 49152;        // 4608 (pitch 36)
    float* x_t  = h_t + 4608;         // 1152 (pitch 36)
    float* y_s  = x_t + 1152;         // 256
    float* th_s = y_s + 256;          // 256
    float* u_s  = th_s + 256;         // 128
    float* dt_s = u_s + 128;          // 32

    const int t    = threadIdx.x;
    const int w    = t >> 5;
    const int lane = t & 31;
    const int j    = w * 8 + (lane >> 2);   // this thread's hidden index
    const int rq   = (lane & 3) << 3;       // row quarter start: 0/8/16/24
    const int R0   = blockIdx.x * M_ROWS;

    // Stage weights into smem
    {
        const float4* src = (const float4*)g_whh_t;
        float4* dst = (float4*)whh;
        #pragma unroll 4
        for (int i = t; i < 49152 / 4; i += THREADS) dst[i] = src[i];
    }
    for (int i = t; i < 4608; i += THREADS) h_t[i] = 0.f;
    if (t < M_ROWS) {
        #pragma unroll
        for (int i = 0; i < 5; ++i)
            y_s[t * 8 + i] = y0[(R0 + t) * 5 + i] + 0.01f;
    }

    // Per-thread biases (j fixed for whole sequence), pre-duplicated
    const u64 bR2  = dup2(b_ih[j] + b_hh[j]);
    const u64 bZ2  = dup2(b_ih[128 + j] + b_hh[128 + j]);
    const u64 bNI2 = dup2(b_ih[256 + j]);
    const u64 bNH2 = dup2(b_hh[256 + j]);
    const float* wj = g_wih_j + j * 96;
    __syncthreads();

    for (int k = 0; k < K_STEPS; ++k) {
        // ---------- stage 1: lift + silu -> x_t[l][r] (2 l's per thread) ----------
        {
            int r  = t & 31;
            int lg = t >> 5;            // 0..15
            float f[8];
            const float* up = u_seq + ((size_t)(R0 + r) * K_STEPS + k) * U_DIM;
            f[0] = up[0]; f[1] = up[1]; f[2] = up[2];
            #pragma unroll
            for (int i = 0; i < 5; ++i) f[3 + i] = y_s[r * 8 + i];
            if (lg == 0) {
                u_s[r * 4 + 0] = f[0];
                u_s[r * 4 + 1] = f[1];
                u_s[r * 4 + 2] = f[2];
                dt_s[r] = dt_seq[(size_t)(R0 + r) * K_STEPS + k];
            }
            #pragma unroll
            for (int c = 0; c < 2; ++c) {
                int l = lg * 2 + c;
                float acc = lift_b[l];
                #pragma unroll
                for (int q = 0; q < 8; ++q)
                    acc = fmaf(lift_W[l * 8 + q], f[q], acc);
                x_t[l * 36 + r] = acc * sigmoidf_(acc);
            }
        }
        __syncthreads();

        // ---------- stage 2: GEMMs (f32x2, row pairs packed; 8 rows/thread) ----------
        u64 aR[4], aZ[4], aNI[4], aNH[4];
        #pragma unroll
        for (int i = 0; i < 4; ++i) {
            aR[i] = bR2; aZ[i] = bZ2; aNI[i] = bNI2; aNH[i] = bNH2;
        }

        // gi: x in smem, W_ih[j] rows from L2
        {
            float4 wR4 = __ldg((const float4*)(wj + 0));
            float4 wZ4 = __ldg((const float4*)(wj + 32));
            float4 wN4 = __ldg((const float4*)(wj + 64));
            #pragma unroll
            for (int l0 = 0; l0 < 32; l0 += 4) {
                float wRv[4], wZv[4], wNv[4];
                *(float4*)wRv = wR4; *(float4*)wZv = wZ4; *(float4*)wNv = wN4;
                if (l0 + 4 < 32) {
                    wR4 = __ldg((const float4*)(wj + l0 + 4));
                    wZ4 = __ldg((const float4*)(wj + 32 + l0 + 4));
                    wN4 = __ldg((const float4*)(wj + 64 + l0 + 4));
                }
                #pragma unroll
                for (int dl = 0; dl < 4; ++dl) {
                    const int l = l0 + dl;
                    const ulonglong2* xp = (const ulonglong2*)(x_t + l * 36 + rq);
                    ulonglong2 x01 = xp[0], x23 = xp[1];
                    u64 xv[4] = {x01.x, x01.y, x23.x, x23.y};
                    u64 wr2 = dup2(wRv[dl]), wz2 = dup2(wZv[dl]), wn2 = dup2(wNv[dl]);
                    #pragma unroll
                    for (int i = 0; i < 4; ++i) {
                        aR[i]  = fma2(xv[i], wr2, aR[i]);
                        aZ[i]  = fma2(xv[i], wz2, aZ[i]);
                        aNI[i] = fma2(xv[i], wn2, aNI[i]);
                    }
                }
            }
        }

        // gh: h + W_hh from smem. 4-lane groups share j (broadcast weights);
        // quarter-row blocks per lane.
        #pragma unroll 4
        for (int kk = 0; kk < 128; ++kk) {
            const float* wrow = whh + kk * 384 + j;
            u64 wr2 = dup2(wrow[0]);
            u64 wz2 = dup2(wrow[128]);
            u64 wn2 = dup2(wrow[256]);
            const ulonglong2* hp = (const ulonglong2*)(h_t + kk * 36 + rq);
            ulonglong2 h01 = hp[0], h23 = hp[1];
            u64 hv[4] = {h01.x, h01.y, h23.x, h23.y};
            #pragma unroll
            for (int i = 0; i < 4; ++i) {
                aR[i]  = fma2(hv[i], wr2, aR[i]);
                aZ[i]  = fma2(hv[i], wz2, aZ[i]);
                aNH[i] = fma2(hv[i], wn2, aNH[i]);
            }
        }

        // gates + h update (this thread owns h[j][rq..rq+7])
        float hn[8];
        {
            const ulonglong2* hop = (const ulonglong2*)(h_t + j * 36 + rq);
            ulonglong2 ho01 = hop[0], ho23 = hop[1];
            u64 hov[4] = {ho01.x, ho01.y, ho23.x, ho23.y};
            #pragma unroll
            for (int i = 0; i < 4; ++i) {
                float r0, r1, z0, z1, ni0, ni1, nh0, nh1, h0, h1;
                unpack2(aR[i], r0, r1);
                unpack2(aZ[i], z0, z1);
                unpack2(aNI[i], ni0, ni1);
                unpack2(aNH[i], nh0, nh1);
                unpack2(hov[i], h0, h1);
                float gr0 = sigmoidf_(r0), gr1 = sigmoidf_(r1);
                float gz0 = sigmoidf_(z0), gz1 = sigmoidf_(z1);
                float gn0 = tanhf_(fmaf(gr0, nh0, ni0));
                float gn1 = tanhf_(fmaf(gr1, nh1, ni1));
                hn[2 * i]     = (1.f - gz0) * gn0 + gz0 * h0;
                hn[2 * i + 1] = (1.f - gz1) * gn1 + gz1 * h1;
            }
        }

        __syncthreads();  // all reads of h_t complete
        {
            float4* hdst = (float4*)(h_t + j * 36 + rq);
            hdst[0] = make_float4(hn[0], hn[1], hn[2], hn[3]);
            hdst[1] = make_float4(hn[4], hn[5], hn[6], hn[7]);
        }
        __syncthreads();

        // ---------- stage 3: head -> theta ----------
        if (t < 256) {
            int r = t >> 3, c8 = t & 7;
            float acc = head_b[c8];
            #pragma unroll 4
            for (int jj = 0; jj < 128; jj += 4) {
                const float4 wv = __ldg((const float4*)(head_W + c8 * 128 + jj));
                acc = fmaf(wv.x, h_t[(jj + 0) * 36 + r], acc);
                acc = fmaf(wv.y, h_t[(jj + 1) * 36 + r], acc);
                acc = fmaf(wv.z, h_t[(jj + 2) * 36 + r], acc);
                acc = fmaf(wv.w, h_t[(jj + 3) * 36 + r], acc);
            }
            float th = 0.01f + 2.99f * sigmoidf_(acc);
            th_s[r * 8 + c8] = th;
            theta_out[(((size_t)(R0 + r)) * K_STEPS + k) * 8 + c8] = th;
        }
        __syncthreads();

        // ---------- stage 4: RK4 ODE (one lane per row) ----------
        if (t < 32) {
            int r = t;
            float y[5];
            #pragma unroll
            for (int i = 0; i < 5; ++i) y[i] = y_s[r * 8 + i];
            float u0 = u_s[r * 4 + 0], u1 = u_s[r * 4 + 1], u2 = u_s[r * 4 + 2];
            #pragma unroll
            for (int p = 0; p < 5; ++p)
                y[p] += u0 * ujump[p] + u1 * ujump[5 + p] + u2 * ujump[10 + p];
            float th[8];
            #pragma unroll
            for (int i = 0; i < 8; ++i) th[i] = th_s[r * 8 + i];
            float hs = dt_s[r] * 0.1f;
            float hh = 0.5f * hs;
            float h6 = hs * (1.f / 6.f);
            for (int s = 0; s < 10; ++s) {
                float k1[5], k2[5], k3[5], k4[5], yt[5];
                rhs5(y, th, k1);
                #pragma unroll
                for (int i = 0; i < 5; ++i) yt[i] = fmaf(hh, k1[i], y[i]);
                rhs5(yt, th, k2);
                #pragma unroll
                for (int i = 0; i < 5; ++i) yt[i] = fmaf(hh, k2[i], y[i]);
                rhs5(yt, th, k3);
                #pragma unroll
                for (int i = 0; i < 5; ++i) yt[i] = fmaf(hs, k3[i], y[i]);
                rhs5(yt, th, k4);
                #pragma unroll
                for (int i = 0; i < 5; ++i) {
                    float incr = k1[i] + 2.f * k2[i] + 2.f * k3[i] + k4[i];
                    y[i] = fmaxf(fmaf(h6, incr, y[i]), 0.f);
                }
            }
            #pragma unroll
            for (int i = 0; i < 5; ++i) {
                y_s[r * 8 + i] = y[i];
                y_out[(((size_t)(R0 + r)) * K_STEPS + k) * 5 + i] = y[i];
            }
        }
        __syncthreads();
    }
}

extern "C" void kernel_launch(void* const* d_in, const int* in_sizes, int n_in,
                              void* d_out, int out_size) {
    const float* y0     = (const float*)d_in[0];
    const float* u_seq  = (const float*)d_in[1];
    const float* dt_seq = (const float*)d_in[2];
    const float* lift_W = (const float*)d_in[3];
    const float* lift_b = (const float*)d_in[4];
    const float* W_ih   = (const float*)d_in[5];
    const float* W_hh   = (const float*)d_in[6];
    const float* b_ih   = (const float*)d_in[7];
    const float* b_hh   = (const float*)d_in[8];
    const float* head_W = (const float*)d_in[9];
    const float* head_b = (const float*)d_in[10];
    const float* ujump  = (const float*)d_in[11];

    float* y_out     = (float*)d_out;
    float* theta_out = y_out + (size_t)B_TOT * K_STEPS * 5;

    prep_kernel<<<(384 * 128 + 255) / 256, 256>>>(W_ih, W_hh);

    size_t smem_bytes = (size_t)SM_TOTAL_FLOATS * sizeof(float);  // 222336
    cudaFuncSetAttribute(rnn_main, cudaFuncAttributeMaxDynamicSharedMemorySize,
                         (int)smem_bytes);
    rnn_main<<<B_TOT / M_ROWS, THREADS, smem_bytes>>>(
        y0, u_seq, dt_seq, lift_W, lift_b, b_ih, b_hh, head_W, head_b, ujump,
        y_out, theta_out);
}

// round 7
// speedup vs baseline: 2.8049x; 2.8007x over previous
#include <cuda_runtime.h>
#include <cuda_fp16.h>
#include <cstdint>

typedef unsigned int u32;

#define B_TOT   4096
#define K_STEPS 512
#define M_ROWS  32
#define THREADS 256

// smem pitches (elements)
#define H16_PITCH 136   // halves  (128 + 8 pad)  -> conflict-free B-frag LDS
#define X16_PITCH 40    // halves  (32 + 8 pad)
#define H32_PITCH 132   // floats  (128 + 4 pad)

__device__ __forceinline__ u32 packh2(float a, float b) {
    __half2 h = __floats2half2_rn(a, b);
    return *(u32*)&h;
}
__device__ __forceinline__ float sigmoidf_(float x) {
    x = fminf(fmaxf(x, -30.f), 30.f);
    return __fdividef(1.f, 1.f + __expf(-x));
}
__device__ __forceinline__ float tanhf_(float x) {
    x = fminf(fmaxf(x, -15.f), 15.f);
    float e = __expf(2.f * x);
    return __fdividef(e - 1.f, e + 1.f);
}
__device__ __forceinline__ void rhs5(const float* y, const float* th, float* d) {
    float f1 = th[0] * y[0] - th[4] * y[1];
    float f2 = th[1] * y[1] - th[5] * y[2];
    float f3 = th[2] * y[2] - th[6] * y[3];
    float f4 = th[3] * y[3] - th[7] * y[4];
    d[0] = -f1; d[1] = f1 - f2; d[2] = f2 - f3; d[3] = f3 - f4; d[4] = f4;
}

// D += A(16x16,row) * B(16x8,col);  C/D m16n8 fp32, A/B fp16
__device__ __forceinline__ void mma4(float* c, const u32* a, u32 b0, u32 b1) {
    asm volatile(
        "mma.sync.aligned.m16n8k16.row.col.f32.f16.f16.f32 "
        "{%0,%1,%2,%3},{%4,%5,%6,%7},{%8,%9},{%0,%1,%2,%3};"
        : "+f"(c[0]), "+f"(c[1]), "+f"(c[2]), "+f"(c[3])
        : "r"(a[0]), "r"(a[1]), "r"(a[2]), "r"(a[3]), "r"(b0), "r"(b1));
}

__global__ void __launch_bounds__(THREADS, 1)
rnn_main(const float* __restrict__ y0,
         const float* __restrict__ u_seq,
         const float* __restrict__ dt_seq,
         const float* __restrict__ lift_W,
         const float* __restrict__ lift_b,
         const float* __restrict__ W_ih,
         const float* __restrict__ W_hh,
         const float* __restrict__ b_ih,
         const float* __restrict__ b_hh,
         const float* __restrict__ head_W,
         const float* __restrict__ head_b,
         const float* __restrict__ ujump,
         float* __restrict__ y_out,
         float* __restrict__ theta_out) {
    __shared__ __half h16[32 * H16_PITCH];   // h fp16 [r][j]
    __shared__ __half x16[32 * X16_PITCH];   // x fp16 [r][l]
    __shared__ float  h32[32 * H32_PITCH];   // h fp32 [r][j]
    __shared__ float  hW_s[1024];            // head_W [8][128]
    __shared__ float  hb_s[8];
    __shared__ float  lW_s[256];             // lift_W [32][8]
    __shared__ float  lb_s[32];
    __shared__ float  y_s[256];              // [r*8+i]
    __shared__ float  th_s[256];
    __shared__ float  u_s[128];
    __shared__ float  dt_s[32];

    const int t = threadIdx.x, w = t >> 5, lane = t & 31;
    const int qr = lane >> 2, qc = lane & 3;     // mma group row / thread-in-group
    const int jw = w * 16;                       // warp's j base
    const int j_lo = jw + qr, j_hi = j_lo + 8;
    const int R0 = blockIdx.x * M_ROWS;

    // ---------------- prologue ----------------
    // W_hh fragments (A, row-major m16k16): permanent registers
    u32 agh[3][8][4];
    #pragma unroll
    for (int g = 0; g < 3; ++g)
        #pragma unroll
        for (int s = 0; s < 8; ++s) {
            const float* p = W_hh + (g * 128 + j_lo) * 128 + 16 * s + qc * 2;
            agh[g][s][0] = packh2(p[0], p[1]);
            agh[g][s][1] = packh2(p[1024], p[1025]);   // +8 rows
            agh[g][s][2] = packh2(p[8], p[9]);         // +8 cols
            agh[g][s][3] = packh2(p[1032], p[1033]);
        }
    u32 agi[3][2][4];
    #pragma unroll
    for (int g = 0; g < 3; ++g)
        #pragma unroll
        for (int s = 0; s < 2; ++s) {
            const float* p = W_ih + (g * 128 + j_lo) * 32 + 16 * s + qc * 2;
            agi[g][s][0] = packh2(p[0], p[1]);
            agi[g][s][1] = packh2(p[256], p[257]);     // +8 rows (stride 32)
            agi[g][s][2] = packh2(p[8], p[9]);
            agi[g][s][3] = packh2(p[264], p[265]);
        }
    // biases for (j_lo, j_hi)
    const float bR0  = b_ih[j_lo] + b_hh[j_lo];
    const float bR1  = b_ih[j_hi] + b_hh[j_hi];
    const float bZ0  = b_ih[128 + j_lo] + b_hh[128 + j_lo];
    const float bZ1  = b_ih[128 + j_hi] + b_hh[128 + j_hi];
    const float bNI0 = b_ih[256 + j_lo], bNI1 = b_ih[256 + j_hi];
    const float bNH0 = b_hh[256 + j_lo], bNH1 = b_hh[256 + j_hi];

    // smem init
    for (int i = t; i < 32 * H16_PITCH / 2; i += THREADS) ((u32*)h16)[i] = 0;
    for (int i = t; i < 32 * H32_PITCH; i += THREADS) h32[i] = 0.f;
    for (int i = t; i < 1024; i += THREADS) hW_s[i] = head_W[i];
    for (int i = t; i < 256;  i += THREADS) lW_s[i] = lift_W[i];
    if (t < 32) lb_s[t] = lift_b[t];
    if (t < 8)  hb_s[t] = head_b[t];
    if (t < 32) {
        #pragma unroll
        for (int i = 0; i < 5; ++i)
            y_s[t * 8 + i] = y0[(R0 + t) * 5 + i] + 0.01f;
    }
    float uj[15];
    #pragma unroll
    for (int i = 0; i < 15; ++i) uj[i] = ujump[i];
    __syncthreads();

    // lift(kidx): feat=[u, y_prev] -> silu -> x16; also u_s/dt_s
    auto lift = [&](int kidx) {
        int r = t & 31, lg = t >> 5;
        const float* up = u_seq + ((size_t)(R0 + r) * K_STEPS + kidx) * 3;
        float f[8];
        f[0] = up[0]; f[1] = up[1]; f[2] = up[2];
        #pragma unroll
        for (int i = 0; i < 5; ++i) f[3 + i] = y_s[r * 8 + i];
        if (lg == 0) {
            u_s[r * 4 + 0] = f[0]; u_s[r * 4 + 1] = f[1]; u_s[r * 4 + 2] = f[2];
            dt_s[r] = dt_seq[(size_t)(R0 + r) * K_STEPS + kidx];
        }
        #pragma unroll
        for (int c = 0; c < 4; ++c) {
            int l = lg * 4 + c;
            float acc = lb_s[l];
            #pragma unroll
            for (int q = 0; q < 8; ++q) acc = fmaf(lW_s[l * 8 + q], f[q], acc);
            x16[r * X16_PITCH + l] = __float2half_rn(acc * sigmoidf_(acc));
        }
    };

    lift(0);
    __syncthreads();

    // ---------------- main loop ----------------
    for (int k = 0; k < K_STEPS; ++k) {
        // accumulators: [ntile][c0..c3]; c0,c1 -> j_lo, c2,c3 -> j_hi
        float cR[4][4], cZ[4][4], cNI[4][4], cNH[4][4];
        #pragma unroll
        for (int nt = 0; nt < 4; ++nt) {
            cR[nt][0] = bR0;  cR[nt][1] = bR0;  cR[nt][2] = bR1;  cR[nt][3] = bR1;
            cZ[nt][0] = bZ0;  cZ[nt][1] = bZ0;  cZ[nt][2] = bZ1;  cZ[nt][3] = bZ1;
            cNI[nt][0] = bNI0; cNI[nt][1] = bNI0; cNI[nt][2] = bNI1; cNI[nt][3] = bNI1;
            cNH[nt][0] = bNH0; cNH[nt][1] = bNH0; cNH[nt][2] = bNH1; cNH[nt][3] = bNH1;
        }

        // gh: W_hh x h   (B frags from h16, conflict-free LDS.32)
        #pragma unroll
        for (int s = 0; s < 8; ++s) {
            #pragma unroll
            for (int nt = 0; nt < 4; ++nt) {
                int r = qr + 8 * nt;
                u32 b0 = *(const u32*)&h16[r * H16_PITCH + 16 * s + qc * 2];
                u32 b1 = *(const u32*)&h16[r * H16_PITCH + 16 * s + 8 + qc * 2];
                mma4(cR[nt],  agh[0][s], b0, b1);
                mma4(cZ[nt],  agh[1][s], b0, b1);
                mma4(cNH[nt], agh[2][s], b0, b1);
            }
        }
        // gi: W_ih x x
        #pragma unroll
        for (int s = 0; s < 2; ++s) {
            #pragma unroll
            for (int nt = 0; nt < 4; ++nt) {
                int r = qr + 8 * nt;
                u32 b0 = *(const u32*)&x16[r * X16_PITCH + 16 * s + qc * 2];
                u32 b1 = *(const u32*)&x16[r * X16_PITCH + 16 * s + 8 + qc * 2];
                mma4(cR[nt],  agi[0][s], b0, b1);
                mma4(cZ[nt],  agi[1][s], b0, b1);
                mma4(cNI[nt], agi[2][s], b0, b1);
            }
        }

        // gates -> h_new (registers); read old h BEFORE the store barrier
        float hn[4][4];
        #pragma unroll
        for (int nt = 0; nt < 4; ++nt) {
            int r0 = qc * 2 + 8 * nt;
            float ho[4];
            ho[0] = h32[r0 * H32_PITCH + j_lo];
            ho[1] = h32[(r0 + 1) * H32_PITCH + j_lo];
            ho[2] = h32[r0 * H32_PITCH + j_hi];
            ho[3] = h32[(r0 + 1) * H32_PITCH + j_hi];
            #pragma unroll
            for (int c = 0; c < 4; ++c) {
                float gr = sigmoidf_(cR[nt][c]);
                float gz = sigmoidf_(cZ[nt][c]);
                float gn = tanhf_(fmaf(gr, cNH[nt][c], cNI[nt][c]));
                hn[nt][c] = (1.f - gz) * gn + gz * ho[c];
            }
        }
        __syncthreads();   // all h16/h32 reads complete
        #pragma unroll
        for (int nt = 0; nt < 4; ++nt) {
            int r0 = qc * 2 + 8 * nt;
            h32[r0 * H32_PITCH + j_lo]       = hn[nt][0];
            h32[(r0 + 1) * H32_PITCH + j_lo] = hn[nt][1];
            h32[r0 * H32_PITCH + j_hi]       = hn[nt][2];
            h32[(r0 + 1) * H32_PITCH + j_hi] = hn[nt][3];
            h16[r0 * H16_PITCH + j_lo]       = __float2half_rn(hn[nt][0]);
            h16[(r0 + 1) * H16_PITCH + j_lo] = __float2half_rn(hn[nt][1]);
            h16[r0 * H16_PITCH + j_hi]       = __float2half_rn(hn[nt][2]);
            h16[(r0 + 1) * H16_PITCH + j_hi] = __float2half_rn(hn[nt][3]);
        }
        __syncthreads();   // h_k visible

        // head -> theta_k
        {
            int r = t >> 3, c8 = t & 7;
            float acc = hb_s[c8];
            const float4* wv = (const float4*)(hW_s + c8 * 128);
            const float4* hv = (const float4*)(h32 + r * H32_PITCH);
            #pragma unroll 8
            for (int q = 0; q < 32; ++q) {
                float4 a = wv[q], b = hv[q];
                acc = fmaf(a.x, b.x, acc);
                acc = fmaf(a.y, b.y, acc);
                acc = fmaf(a.z, b.z, acc);
                acc = fmaf(a.w, b.w, acc);
            }
            float th = 0.01f + 2.99f * sigmoidf_(acc);
            th_s[r * 8 + c8] = th;
            theta_out[(((size_t)(R0 + r)) * K_STEPS + k) * 8 + c8] = th;
        }
        __syncthreads();

        // RK4 (warp 0, lane = batch row)
        if (t < 32) {
            int r = t;
            float y[5];
            #pragma unroll
            for (int i = 0; i < 5; ++i) y[i] = y_s[r * 8 + i];
            float u0 = u_s[r * 4], u1 = u_s[r * 4 + 1], u2 = u_s[r * 4 + 2];
            #pragma unroll
            for (int p = 0; p < 5; ++p)
                y[p] += u0 * uj[p] + u1 * uj[5 + p] + u2 * uj[10 + p];
            float th[8];
            #pragma unroll
            for (int i = 0; i < 8; ++i) th[i] = th_s[r * 8 + i];
            float hs = dt_s[r] * 0.1f, hh = 0.5f * hs, h6 = hs * (1.f / 6.f);
            for (int s = 0; s < 10; ++s) {
                float k1[5], k2[5], k3[5], k4[5], yt[5];
                rhs5(y, th, k1);
                #pragma unroll
                for (int i = 0; i < 5; ++i) yt[i] = fmaf(hh, k1[i], y[i]);
                rhs5(yt, th, k2);
                #pragma unroll
                for (int i = 0; i < 5; ++i) yt[i] = fmaf(hh, k2[i], y[i]);
                rhs5(yt, th, k3);
                #pragma unroll
                for (int i = 0; i < 5; ++i) yt[i] = fmaf(hs, k3[i], y[i]);
                rhs5(yt, th, k4);
                #pragma unroll
                for (int i = 0; i < 5; ++i) {
                    float incr = k1[i] + 2.f * k2[i] + 2.f * k3[i] + k4[i];
                    y[i] = fmaxf(fmaf(h6, incr, y[i]), 0.f);
                }
            }
            #pragma unroll
            for (int i = 0; i < 5; ++i) {
                y_s[r * 8 + i] = y[i];
                y_out[(((size_t)(R0 + r)) * K_STEPS + k) * 5 + i] = y[i];
            }
        }
        __syncthreads();

        if (k + 1 < K_STEPS) {
            lift(k + 1);
            __syncthreads();
        }
    }
}

extern "C" void kernel_launch(void* const* d_in, const int* in_sizes, int n_in,
                              void* d_out, int out_size) {
    const float* y0     = (const float*)d_in[0];
    const float* u_seq  = (const float*)d_in[1];
    const float* dt_seq = (const float*)d_in[2];
    const float* lift_W = (const float*)d_in[3];
    const float* lift_b = (const float*)d_in[4];
    const float* W_ih   = (const float*)d_in[5];
    const float* W_hh   = (const float*)d_in[6];
    const float* b_ih   = (const float*)d_in[7];
    const float* b_hh   = (const float*)d_in[8];
    const float* head_W = (const float*)d_in[9];
    const float* head_b = (const float*)d_in[10];
    const float* ujump  = (const float*)d_in[11];

    float* y_out     = (float*)d_out;
    float* theta_out = y_out + (size_t)B_TOT * K_STEPS * 5;

    rnn_main<<<B_TOT / M_ROWS, THREADS>>>(
        y0, u_seq, dt_seq, lift_W, lift_b, W_ih, W_hh, b_ih, b_hh,
        head_W, head_b, ujump, y_out, theta_out);
}